// round 1
// baseline (speedup 1.0000x reference)
#include <cuda_runtime.h>

// DualBiPlane: dual bilinear gather from Fxy[4,400,400,16] and Fuv[4,400,400,16]
// Layout: inputs m(int32,N), h(float32,N*2), u(float32,N), v(float32,N),
//         Fxy(float32, 4*400*400*16), Fuv(float32, 4*400*400*16)
// Output: float32 (N, 32) = concat(lat_xy[16], lat_uv[16])
//
// Strategy: 4 threads per sample. Each lane owns 4 of the 16 channels (one
// float4) of each of the two tables. A corner gather is then 4 lanes x 16B
// = one coalesced 64B request (2 sectors) -> minimal L2 sector traffic for
// a random gather. Tables (82 MB total) are L2-resident, so this kernel is
// expected to be L2-bandwidth bound.

#define RES   400
#define NLANE 4   // threads per sample; 16 channels / 4 floats

__device__ __forceinline__ float4 bilerp4(const float4* __restrict__ F,
                                          int mi, float fi, float fj, int lane)
{
    int   i1 = (int)floorf(fi);
    int   j1 = (int)floorf(fj);
    float ir = fi - (float)i1;
    float jr = fj - (float)j1;
    int   i2 = i1 + 1; if (i2 == RES) i2 = 0;
    int   j2 = j1 + 1; if (j2 == RES) j2 = 0;

    int base = mi * (RES * RES);
    int r1   = (base + i1 * RES);
    int r2   = (base + i2 * RES);

    // float4 index: ((m*RES + i)*RES + j)*4 + lane
    float4 g00 = __ldg(F + (r1 + j1) * 4 + lane);
    float4 g10 = __ldg(F + (r2 + j1) * 4 + lane);
    float4 g01 = __ldg(F + (r1 + j2) * 4 + lane);
    float4 g11 = __ldg(F + (r2 + j2) * 4 + lane);

    float w00 = (1.0f - ir) * (1.0f - jr);
    float w10 = ir * (1.0f - jr);
    float w01 = (1.0f - ir) * jr;
    float w11 = ir * jr;

    float4 r;
    r.x = g00.x * w00 + g10.x * w10 + g01.x * w01 + g11.x * w11;
    r.y = g00.y * w00 + g10.y * w10 + g01.y * w01 + g11.y * w11;
    r.z = g00.z * w00 + g10.z * w10 + g01.z * w01 + g11.z * w11;
    r.w = g00.w * w00 + g10.w * w10 + g01.w * w01 + g11.w * w11;
    return r;
}

__global__ __launch_bounds__(256)
void dualbiplane_kernel(const int*    __restrict__ m,
                        const float2* __restrict__ h,
                        const float*  __restrict__ u,
                        const float*  __restrict__ v,
                        const float4* __restrict__ Fxy,
                        const float4* __restrict__ Fuv,
                        float4*       __restrict__ out,
                        int N)
{
    int t    = blockIdx.x * blockDim.x + threadIdx.x;
    int n    = t >> 2;        // sample index
    int lane = t & 3;         // channel group (4 floats) within sample
    if (n >= N) return;

    int    mi = __ldg(m + n);
    float2 hh = __ldg(h + n);
    float  uu = __ldg(u + n);
    float  vv = __ldg(v + n);

    // index computation mirrors the reference exactly
    float ix = (hh.x + 1.0f) * 0.5f * 400.0f; if (ix == 400.0f) ix = 399.0f;
    float iy = (hh.y + 1.0f) * 0.5f * 400.0f; if (iy == 400.0f) iy = 399.0f;
    float iu = uu * 400.0f;                   if (iu == 400.0f) iu = 399.0f;
    float iv = vv * 400.0f;                   if (iv == 400.0f) iv = 399.0f;

    float4 rxy = bilerp4(Fxy, mi, ix, iy, lane);
    float4 ruv = bilerp4(Fuv, mi, iu, iv, lane);

    // out sample n occupies 8 float4s: [0..3]=xy channels, [4..7]=uv channels
    out[n * 8 + lane]     = rxy;
    out[n * 8 + 4 + lane] = ruv;
}

extern "C" void kernel_launch(void* const* d_in, const int* in_sizes, int n_in,
                              void* d_out, int out_size)
{
    const int*    m   = (const int*)   d_in[0];
    const float2* h   = (const float2*)d_in[1];
    const float*  u   = (const float*) d_in[2];
    const float*  v   = (const float*) d_in[3];
    const float4* Fxy = (const float4*)d_in[4];
    const float4* Fuv = (const float4*)d_in[5];

    int N = in_sizes[0];
    long long total_threads = (long long)N * NLANE;
    int threads = 256;
    int blocks  = (int)((total_threads + threads - 1) / threads);

    dualbiplane_kernel<<<blocks, threads>>>(m, h, u, v, Fxy, Fuv,
                                            (float4*)d_out, N);
}

// round 3
// speedup vs baseline: 1.0269x; 1.0269x over previous
#include <cuda_runtime.h>
#include <cstdint>

// DualBiPlane: dual bilinear gather from Fxy[4,400,400,16] and Fuv[4,400,400,16]
// Output: float32 (N, 32) = concat(lat_xy[16], lat_uv[16])
//
// Round 3: same as round 2 (L2-policy-controlled gather) but using the
// createpolicy + L2::cache_hint form, since this ptxas rejects the direct
// .L2::evict_last modifier on v4.f32 loads.
//   - table gathers:  ld.global.nc.L2::cache_hint (policy = evict_last 1.0)
//   - output stores:  st.global.cs                (evict-first, write-once)
//   - scalar inputs:  __ldcs                      (streaming, read-once)

#define RES   400
#define NLANE 4   // threads per sample; 16 channels / 4 float4-groups

__device__ __forceinline__ uint64_t mk_evict_last_policy()
{
    uint64_t p;
    asm("createpolicy.fractional.L2::evict_last.b64 %0, 1.0;" : "=l"(p));
    return p;
}

__device__ __forceinline__ float4 ld_table(const float4* __restrict__ p,
                                           uint64_t pol)
{
    float4 g;
    asm volatile("ld.global.nc.L2::cache_hint.v4.f32 {%0,%1,%2,%3}, [%4], %5;"
                 : "=f"(g.x), "=f"(g.y), "=f"(g.z), "=f"(g.w)
                 : "l"(p), "l"(pol));
    return g;
}

__device__ __forceinline__ void st_stream(float4* p, float4 v)
{
    asm volatile("st.global.cs.v4.f32 [%0], {%1,%2,%3,%4};"
                 :: "l"(p), "f"(v.x), "f"(v.y), "f"(v.z), "f"(v.w));
}

__device__ __forceinline__ float4 bilerp4(const float4* __restrict__ F,
                                          int mi, float fi, float fj, int lane,
                                          uint64_t pol)
{
    int   i1 = (int)floorf(fi);
    int   j1 = (int)floorf(fj);
    float ir = fi - (float)i1;
    float jr = fj - (float)j1;
    int   i2 = i1 + 1; if (i2 == RES) i2 = 0;
    int   j2 = j1 + 1; if (j2 == RES) j2 = 0;

    int base = mi * (RES * RES);
    int r1   = (base + i1 * RES);
    int r2   = (base + i2 * RES);

    float4 g00 = ld_table(F + (size_t)(r1 + j1) * 4 + lane, pol);
    float4 g10 = ld_table(F + (size_t)(r2 + j1) * 4 + lane, pol);
    float4 g01 = ld_table(F + (size_t)(r1 + j2) * 4 + lane, pol);
    float4 g11 = ld_table(F + (size_t)(r2 + j2) * 4 + lane, pol);

    float w00 = (1.0f - ir) * (1.0f - jr);
    float w10 = ir * (1.0f - jr);
    float w01 = (1.0f - ir) * jr;
    float w11 = ir * jr;

    float4 r;
    r.x = g00.x * w00 + g10.x * w10 + g01.x * w01 + g11.x * w11;
    r.y = g00.y * w00 + g10.y * w10 + g01.y * w01 + g11.y * w11;
    r.z = g00.z * w00 + g10.z * w10 + g01.z * w01 + g11.z * w11;
    r.w = g00.w * w00 + g10.w * w10 + g01.w * w01 + g11.w * w11;
    return r;
}

__global__ __launch_bounds__(256)
void dualbiplane_kernel(const int*    __restrict__ m,
                        const float2* __restrict__ h,
                        const float*  __restrict__ u,
                        const float*  __restrict__ v,
                        const float4* __restrict__ Fxy,
                        const float4* __restrict__ Fuv,
                        float4*       __restrict__ out,
                        int N)
{
    int t    = blockIdx.x * blockDim.x + threadIdx.x;
    int n    = t >> 2;        // sample index
    int lane = t & 3;         // channel group (4 floats) within sample
    if (n >= N) return;

    uint64_t pol = mk_evict_last_policy();

    int    mi = __ldcs(m + n);
    float2 hh = __ldcs(h + n);
    float  uu = __ldcs(u + n);
    float  vv = __ldcs(v + n);

    // index computation mirrors the reference exactly
    float ix = (hh.x + 1.0f) * 0.5f * 400.0f; if (ix == 400.0f) ix = 399.0f;
    float iy = (hh.y + 1.0f) * 0.5f * 400.0f; if (iy == 400.0f) iy = 399.0f;
    float iu = uu * 400.0f;                   if (iu == 400.0f) iu = 399.0f;
    float iv = vv * 400.0f;                   if (iv == 400.0f) iv = 399.0f;

    float4 rxy = bilerp4(Fxy, mi, ix, iy, lane, pol);
    float4 ruv = bilerp4(Fuv, mi, iu, iv, lane, pol);

    // out sample n occupies 8 float4s: [0..3]=xy channels, [4..7]=uv channels
    st_stream(out + (size_t)n * 8 + lane,     rxy);
    st_stream(out + (size_t)n * 8 + 4 + lane, ruv);
}

extern "C" void kernel_launch(void* const* d_in, const int* in_sizes, int n_in,
                              void* d_out, int out_size)
{
    const int*    m   = (const int*)   d_in[0];
    const float2* h   = (const float2*)d_in[1];
    const float*  u   = (const float*) d_in[2];
    const float*  v   = (const float*) d_in[3];
    const float4* Fxy = (const float4*)d_in[4];
    const float4* Fuv = (const float4*)d_in[5];

    int N = in_sizes[0];
    long long total_threads = (long long)N * NLANE;
    int threads = 256;
    int blocks  = (int)((total_threads + threads - 1) / threads);

    dualbiplane_kernel<<<blocks, threads>>>(m, h, u, v, Fxy, Fuv,
                                            (float4*)d_out, N);
}

// round 4
// speedup vs baseline: 1.1401x; 1.1102x over previous
#include <cuda_runtime.h>
#include <cuda_fp16.h>
#include <cstdint>

// DualBiPlane round 4: fp16 table compaction.
//
// The fp32 tables (82 MB) would not stay L2-resident against the 256 MB/launch
// output stream (R3 profile: still ~430 MB of table re-reads). Convert both
// tables to fp16 (41 MB) in __device__ scratch each launch, then gather fp16:
//   - table footprint halves -> L2-resident even under streaming pressure
//   - each corner fetch = 16ch x 2B = exactly one 32B sector (sector traffic /2)
// Interp math stays fp32; fp16 rounding ~2^-11 << 1e-3 threshold.

#define RES        400
#define TAB_ELEMS  (4 * RES * RES * 16)   // 10,240,000 halfs per table

__device__ __half g_Fxy_h[TAB_ELEMS];
__device__ __half g_Fuv_h[TAB_ELEMS];

// ---------------------------------------------------------------------------
// cache policy helpers
// ---------------------------------------------------------------------------
__device__ __forceinline__ uint64_t mk_evict_last_policy()
{
    uint64_t p;
    asm("createpolicy.fractional.L2::evict_last.b64 %0, 1.0;" : "=l"(p));
    return p;
}

__device__ __forceinline__ uint2 ld_tab8(const uint2* __restrict__ p, uint64_t pol)
{
    uint2 g;
    asm volatile("ld.global.nc.L2::cache_hint.v2.b32 {%0,%1}, [%2], %3;"
                 : "=r"(g.x), "=r"(g.y) : "l"(p), "l"(pol));
    return g;
}

__device__ __forceinline__ void st_tab16(uint4* p, uint4 v, uint64_t pol)
{
    asm volatile("st.global.L2::cache_hint.v4.b32 [%0], {%1,%2,%3,%4}, %5;"
                 :: "l"(p), "r"(v.x), "r"(v.y), "r"(v.z), "r"(v.w), "l"(pol));
}

__device__ __forceinline__ void st_stream(float4* p, float4 v)
{
    asm volatile("st.global.cs.v4.f32 [%0], {%1,%2,%3,%4};"
                 :: "l"(p), "f"(v.x), "f"(v.y), "f"(v.z), "f"(v.w));
}

__device__ __forceinline__ unsigned pack2(float a, float b)
{
    __half2 h = __floats2half2_rn(a, b);
    return *reinterpret_cast<unsigned*>(&h);
}

// ---------------------------------------------------------------------------
// conversion kernel: fp32 tables -> fp16 scratch (runs every launch)
// each thread converts 8 elements (two float4 reads -> one uint4 write)
// ---------------------------------------------------------------------------
__global__ __launch_bounds__(256)
void convert_kernel(const float4* __restrict__ Fxy,
                    const float4* __restrict__ Fuv)
{
    const int PER_TABLE = TAB_ELEMS / 8;  // 1,280,000 threads per table
    int t = blockIdx.x * blockDim.x + threadIdx.x;

    const float4* src;
    __half* dst;
    int i;
    if (t < PER_TABLE)              { src = Fxy; dst = g_Fxy_h; i = t; }
    else if (t < 2 * PER_TABLE)     { src = Fuv; dst = g_Fuv_h; i = t - PER_TABLE; }
    else return;

    uint64_t pol = mk_evict_last_policy();

    float4 a = __ldcs(src + (size_t)i * 2);
    float4 b = __ldcs(src + (size_t)i * 2 + 1);

    uint4 o;
    o.x = pack2(a.x, a.y);
    o.y = pack2(a.z, a.w);
    o.z = pack2(b.x, b.y);
    o.w = pack2(b.z, b.w);

    st_tab16(reinterpret_cast<uint4*>(dst) + i, o, pol);
}

// ---------------------------------------------------------------------------
// gather kernel: 4 lanes per sample, each lane owns 4 channels (8B fp16)
// ---------------------------------------------------------------------------
__device__ __forceinline__ float4 bilerp4_h(const __half* __restrict__ F,
                                            int mi, float fi, float fj,
                                            int lane, uint64_t pol)
{
    int   i1 = (int)floorf(fi);
    int   j1 = (int)floorf(fj);
    float ir = fi - (float)i1;
    float jr = fj - (float)j1;
    int   i2 = i1 + 1; if (i2 == RES) i2 = 0;
    int   j2 = j1 + 1; if (j2 == RES) j2 = 0;

    int base = mi * (RES * RES);
    int r1   = base + i1 * RES;
    int r2   = base + i2 * RES;

    // uint2 element index: ((m*RES+i)*RES+j)*4 + lane  (4 halfs per uint2)
    const uint2* T = reinterpret_cast<const uint2*>(F);
    uint2 d00 = ld_tab8(T + (size_t)(r1 + j1) * 4 + lane, pol);
    uint2 d10 = ld_tab8(T + (size_t)(r2 + j1) * 4 + lane, pol);
    uint2 d01 = ld_tab8(T + (size_t)(r1 + j2) * 4 + lane, pol);
    uint2 d11 = ld_tab8(T + (size_t)(r2 + j2) * 4 + lane, pol);

    float w00 = (1.0f - ir) * (1.0f - jr);
    float w10 = ir * (1.0f - jr);
    float w01 = (1.0f - ir) * jr;
    float w11 = ir * jr;

    float2 a00 = __half22float2(*reinterpret_cast<__half2*>(&d00.x));
    float2 b00 = __half22float2(*reinterpret_cast<__half2*>(&d00.y));
    float2 a10 = __half22float2(*reinterpret_cast<__half2*>(&d10.x));
    float2 b10 = __half22float2(*reinterpret_cast<__half2*>(&d10.y));
    float2 a01 = __half22float2(*reinterpret_cast<__half2*>(&d01.x));
    float2 b01 = __half22float2(*reinterpret_cast<__half2*>(&d01.y));
    float2 a11 = __half22float2(*reinterpret_cast<__half2*>(&d11.x));
    float2 b11 = __half22float2(*reinterpret_cast<__half2*>(&d11.y));

    float4 r;
    r.x = a00.x * w00 + a10.x * w10 + a01.x * w01 + a11.x * w11;
    r.y = a00.y * w00 + a10.y * w10 + a01.y * w01 + a11.y * w11;
    r.z = b00.x * w00 + b10.x * w10 + b01.x * w01 + b11.x * w11;
    r.w = b00.y * w00 + b10.y * w10 + b01.y * w01 + b11.y * w11;
    return r;
}

__global__ __launch_bounds__(256)
void dualbiplane_kernel(const int*    __restrict__ m,
                        const float2* __restrict__ h,
                        const float*  __restrict__ u,
                        const float*  __restrict__ v,
                        float4*       __restrict__ out,
                        int N)
{
    int t    = blockIdx.x * blockDim.x + threadIdx.x;
    int n    = t >> 2;        // sample index
    int lane = t & 3;         // channel group (4 halfs) within sample
    if (n >= N) return;

    uint64_t pol = mk_evict_last_policy();

    int    mi = __ldcs(m + n);
    float2 hh = __ldcs(h + n);
    float  uu = __ldcs(u + n);
    float  vv = __ldcs(v + n);

    // index computation mirrors the reference exactly
    float ix = (hh.x + 1.0f) * 0.5f * 400.0f; if (ix == 400.0f) ix = 399.0f;
    float iy = (hh.y + 1.0f) * 0.5f * 400.0f; if (iy == 400.0f) iy = 399.0f;
    float iu = uu * 400.0f;                   if (iu == 400.0f) iu = 399.0f;
    float iv = vv * 400.0f;                   if (iv == 400.0f) iv = 399.0f;

    float4 rxy = bilerp4_h(g_Fxy_h, mi, ix, iy, lane, pol);
    float4 ruv = bilerp4_h(g_Fuv_h, mi, iu, iv, lane, pol);

    st_stream(out + (size_t)n * 8 + lane,     rxy);
    st_stream(out + (size_t)n * 8 + 4 + lane, ruv);
}

extern "C" void kernel_launch(void* const* d_in, const int* in_sizes, int n_in,
                              void* d_out, int out_size)
{
    const int*    m   = (const int*)   d_in[0];
    const float2* h   = (const float2*)d_in[1];
    const float*  u   = (const float*) d_in[2];
    const float*  v   = (const float*) d_in[3];
    const float4* Fxy = (const float4*)d_in[4];
    const float4* Fuv = (const float4*)d_in[5];

    int N = in_sizes[0];

    // 1) convert fp32 tables -> fp16 scratch (every launch; deterministic)
    {
        int total = 2 * (TAB_ELEMS / 8);
        convert_kernel<<<(total + 255) / 256, 256>>>(Fxy, Fuv);
    }

    // 2) gather
    {
        long long total_threads = (long long)N * 4;
        int blocks = (int)((total_threads + 255) / 256);
        dualbiplane_kernel<<<blocks, 256>>>(m, h, u, v, (float4*)d_out, N);
    }
}

// round 5
// speedup vs baseline: 1.2469x; 1.0937x over previous
#include <cuda_runtime.h>
#include <cuda_fp16.h>
#include <cstdint>

// DualBiPlane round 5: merged corner loads + wide stores.
//
// R4 profile: gather kernel L1-bound (82.8%) at ~9.3 L1 wavefronts/sample.
// fp16 makes the (j1,j1+1) corner pair a contiguous 64B block, so a 4-lane
// quad can fetch a whole row-pair in ONE load instruction (lane q reads 16B
// at j = j1+(q>=2), chunk = (q&1)). 4 load instrs/thread instead of 8.
// One shfl_xor(2) round completes the j-blend; each lane then owns 8
// contiguous output floats -> single 32B store (st.v4.b64), full 128B
// line per quad. Expected wavefronts/sample ~9.3 -> ~6.3.

#define RES        400
#define TAB_ELEMS  (4 * RES * RES * 16)   // halfs per table

__device__ __half g_Fxy_h[TAB_ELEMS];
__device__ __half g_Fuv_h[TAB_ELEMS];

// ---------------------------------------------------------------------------
__device__ __forceinline__ uint64_t mk_evict_last_policy()
{
    uint64_t p;
    asm("createpolicy.fractional.L2::evict_last.b64 %0, 1.0;" : "=l"(p));
    return p;
}

__device__ __forceinline__ uint4 ld_tab16(const uint4* __restrict__ p, uint64_t pol)
{
    uint4 g;
    asm volatile("ld.global.nc.L2::cache_hint.v4.b32 {%0,%1,%2,%3}, [%4], %5;"
                 : "=r"(g.x), "=r"(g.y), "=r"(g.z), "=r"(g.w)
                 : "l"(p), "l"(pol));
    return g;
}

__device__ __forceinline__ void st_tab16(uint4* p, uint4 v, uint64_t pol)
{
    asm volatile("st.global.L2::cache_hint.v4.b32 [%0], {%1,%2,%3,%4}, %5;"
                 :: "l"(p), "r"(v.x), "r"(v.y), "r"(v.z), "r"(v.w), "l"(pol));
}

__device__ __forceinline__ uint64_t pk64(float a, float b)
{
    return (uint64_t)__float_as_uint(a) | ((uint64_t)__float_as_uint(b) << 32);
}

__device__ __forceinline__ void st_out32(float* p,
                                         const float* f)  // 8 floats, 32B aligned
{
    uint64_t p0 = pk64(f[0], f[1]);
    uint64_t p1 = pk64(f[2], f[3]);
    uint64_t p2 = pk64(f[4], f[5]);
    uint64_t p3 = pk64(f[6], f[7]);
    asm volatile("st.global.cs.v4.b64 [%0], {%1,%2,%3,%4};"
                 :: "l"(p), "l"(p0), "l"(p1), "l"(p2), "l"(p3));
}

__device__ __forceinline__ unsigned pack2(float a, float b)
{
    __half2 hh = __floats2half2_rn(a, b);
    return *reinterpret_cast<unsigned*>(&hh);
}

// i-blend: o[k] = A[k]*(1-r) + B[k]*r  for 8 fp16 channels held in uint4
__device__ __forceinline__ void blend8(float* o, uint4 A, uint4 B, float r)
{
    float w0 = 1.0f - r;
    const unsigned* a = &A.x;
    const unsigned* b = &B.x;
#pragma unroll
    for (int k = 0; k < 4; k++) {
        float2 fa = __half22float2(*reinterpret_cast<const __half2*>(&a[k]));
        float2 fb = __half22float2(*reinterpret_cast<const __half2*>(&b[k]));
        o[2*k]   = fa.x * w0 + fb.x * r;
        o[2*k+1] = fa.y * w0 + fb.y * r;
    }
}

// ---------------------------------------------------------------------------
// conversion kernel: fp32 tables -> fp16 scratch (runs every launch)
// ---------------------------------------------------------------------------
__global__ __launch_bounds__(256)
void convert_kernel(const float4* __restrict__ Fxy,
                    const float4* __restrict__ Fuv)
{
    const int PER_TABLE = TAB_ELEMS / 8;
    int t = blockIdx.x * blockDim.x + threadIdx.x;

    const float4* src;
    __half* dst;
    int i;
    if (t < PER_TABLE)          { src = Fxy; dst = g_Fxy_h; i = t; }
    else if (t < 2 * PER_TABLE) { src = Fuv; dst = g_Fuv_h; i = t - PER_TABLE; }
    else return;

    uint64_t pol = mk_evict_last_policy();

    float4 a = __ldcs(src + (size_t)i * 2);
    float4 b = __ldcs(src + (size_t)i * 2 + 1);

    uint4 o;
    o.x = pack2(a.x, a.y);
    o.y = pack2(a.z, a.w);
    o.z = pack2(b.x, b.y);
    o.w = pack2(b.z, b.w);

    st_tab16(reinterpret_cast<uint4*>(dst) + i, o, pol);
}

// ---------------------------------------------------------------------------
// gather kernel
// ---------------------------------------------------------------------------
__global__ __launch_bounds__(256)
void dualbiplane_kernel(const int*    __restrict__ m,
                        const float2* __restrict__ h,
                        const float*  __restrict__ u,
                        const float*  __restrict__ v,
                        float*        __restrict__ out,
                        int N)
{
    int t = blockIdx.x * blockDim.x + threadIdx.x;
    int n = t >> 2;        // sample index
    int q = t & 3;         // lane within sample quad
    if (n >= N) return;    // grid is exact; guard is belt-and-braces

    uint64_t pol = mk_evict_last_policy();

    int    mi = __ldcs(m + n);
    float2 hh = __ldcs(h + n);
    float  uu = __ldcs(u + n);
    float  vv = __ldcs(v + n);

    // index computation mirrors the reference exactly
    float ix = (hh.x + 1.0f) * 0.5f * 400.0f; if (ix == 400.0f) ix = 399.0f;
    float iy = (hh.y + 1.0f) * 0.5f * 400.0f; if (iy == 400.0f) iy = 399.0f;
    float iu = uu * 400.0f;                   if (iu == 400.0f) iu = 399.0f;
    float iv = vv * 400.0f;                   if (iv == 400.0f) iv = 399.0f;

    // XY: rows from ix, cols from iy
    int   xi1 = (int)floorf(ix), xj1 = (int)floorf(iy);
    float xir = ix - (float)xi1, xjr = iy - (float)xj1;
    int   xi2 = xi1 + 1; if (xi2 == RES) xi2 = 0;
    int   xj2 = xj1 + 1; if (xj2 == RES) xj2 = 0;

    // UV: rows from iu, cols from iv
    int   ui1 = (int)floorf(iu), uj1 = (int)floorf(iv);
    float uir = iu - (float)ui1, ujr = iv - (float)uj1;
    int   ui2 = ui1 + 1; if (ui2 == RES) ui2 = 0;
    int   uj2 = uj1 + 1; if (uj2 == RES) uj2 = 0;

    bool hi = (q >= 2);          // this lane handles the j2 corner slices
    int  c  = q & 1;             // channel chunk: 0 -> ch0-7, 1 -> ch8-15

    int xjs = hi ? xj2 : xj1;
    int ujs = hi ? uj2 : uj1;

    const uint4* TX = reinterpret_cast<const uint4*>(g_Fxy_h);
    const uint4* TU = reinterpret_cast<const uint4*>(g_Fuv_h);

    int xbase = mi * (RES * RES);
    size_t ax1 = ((size_t)(xbase + xi1 * RES + xjs)) * 2 + c;
    size_t ax2 = ((size_t)(xbase + xi2 * RES + xjs)) * 2 + c;
    size_t au1 = ((size_t)(xbase + ui1 * RES + ujs)) * 2 + c;
    size_t au2 = ((size_t)(xbase + ui2 * RES + ujs)) * 2 + c;

    uint4 A = ld_tab16(TX + ax1, pol);   // XY row i1, col jsel, chunk c
    uint4 B = ld_tab16(TX + ax2, pol);   // XY row i2
    uint4 C = ld_tab16(TU + au1, pol);   // UV row i1
    uint4 D = ld_tab16(TU + au2, pol);   // UV row i2

    // i-blend (fp32)
    float tx[8], tu[8];
    blend8(tx, A, B, xir);
    blend8(tu, C, D, uir);

    // j-blend via one shfl_xor(2) round.
    // Lane q<2 needs partner's tx (its j2 slice); lane q>=2 needs partner's tu.
    // Each lane sends the array its partner needs.
    float fin[8];
    float wo = hi ? ujr : (1.0f - xjr);   // weight on own slice
    float wr = hi ? (1.0f - ujr) : xjr;   // weight on received slice
#pragma unroll
    for (int k = 0; k < 8; k++) {
        float send = hi ? tx[k] : tu[k];
        float recv = __shfl_xor_sync(0xffffffffu, send, 2);
        float own  = hi ? tu[k] : tx[k];
        fin[k] = own * wo + recv * wr;
    }

    // Lane q owns 8 contiguous output floats:
    //   q=0: XY ch0-7   q=1: XY ch8-15   q=2: UV ch0-7   q=3: UV ch8-15
    st_out32(out + (size_t)n * 32 + q * 8, fin);
}

extern "C" void kernel_launch(void* const* d_in, const int* in_sizes, int n_in,
                              void* d_out, int out_size)
{
    const int*    m   = (const int*)   d_in[0];
    const float2* h   = (const float2*)d_in[1];
    const float*  u   = (const float*) d_in[2];
    const float*  v   = (const float*) d_in[3];
    const float4* Fxy = (const float4*)d_in[4];
    const float4* Fuv = (const float4*)d_in[5];

    int N = in_sizes[0];

    // 1) convert fp32 tables -> fp16 scratch
    {
        int total = 2 * (TAB_ELEMS / 8);
        convert_kernel<<<(total + 255) / 256, 256>>>(Fxy, Fuv);
    }

    // 2) gather
    {
        long long total_threads = (long long)N * 4;
        int blocks = (int)((total_threads + 255) / 256);
        dualbiplane_kernel<<<blocks, 256>>>(m, h, u, v, (float*)d_out, N);
    }
}

// round 6
// speedup vs baseline: 1.3688x; 1.0977x over previous
#include <cuda_runtime.h>
#include <cuda_fp16.h>
#include <cstdint>

// DualBiPlane round 6:
//  - table gathers via __ldcg (L2-only, no L1 allocation: random gather has
//    ~0% L1 hit rate, so L1 line fills were pure overhead)
//  - blend math in packed __half2 end-to-end (i-blend, packed shuffles,
//    j-blend), converting to fp32 only at the final store. ~25% fewer
//    instructions per thread; attacks the issue=56% / L1=70% mixed regime.
// Tables remain fp16 in __device__ scratch, written L2-evict_last by the
// per-launch convert kernel.

#define RES        400
#define TAB_ELEMS  (4 * RES * RES * 16)   // halfs per table

__device__ __half g_Fxy_h[TAB_ELEMS];
__device__ __half g_Fuv_h[TAB_ELEMS];

// ---------------------------------------------------------------------------
__device__ __forceinline__ uint64_t mk_evict_last_policy()
{
    uint64_t p;
    asm("createpolicy.fractional.L2::evict_last.b64 %0, 1.0;" : "=l"(p));
    return p;
}

__device__ __forceinline__ void st_tab16(uint4* p, uint4 v, uint64_t pol)
{
    asm volatile("st.global.L2::cache_hint.v4.b32 [%0], {%1,%2,%3,%4}, %5;"
                 :: "l"(p), "r"(v.x), "r"(v.y), "r"(v.z), "r"(v.w), "l"(pol));
}

__device__ __forceinline__ uint64_t pk64(float a, float b)
{
    return (uint64_t)__float_as_uint(a) | ((uint64_t)__float_as_uint(b) << 32);
}

__device__ __forceinline__ unsigned pack2(float a, float b)
{
    __half2 hh = __floats2half2_rn(a, b);
    return *reinterpret_cast<unsigned*>(&hh);
}

__device__ __forceinline__ __half2 u2h2(unsigned w)
{
    return *reinterpret_cast<__half2*>(&w);
}
__device__ __forceinline__ unsigned h22u(__half2 h)
{
    return *reinterpret_cast<unsigned*>(&h);
}

// ---------------------------------------------------------------------------
// conversion kernel: fp32 tables -> fp16 scratch (runs every launch)
// ---------------------------------------------------------------------------
__global__ __launch_bounds__(256)
void convert_kernel(const float4* __restrict__ Fxy,
                    const float4* __restrict__ Fuv)
{
    const int PER_TABLE = TAB_ELEMS / 8;
    int t = blockIdx.x * blockDim.x + threadIdx.x;

    const float4* src;
    __half* dst;
    int i;
    if (t < PER_TABLE)          { src = Fxy; dst = g_Fxy_h; i = t; }
    else if (t < 2 * PER_TABLE) { src = Fuv; dst = g_Fuv_h; i = t - PER_TABLE; }
    else return;

    uint64_t pol = mk_evict_last_policy();

    float4 a = __ldcs(src + (size_t)i * 2);
    float4 b = __ldcs(src + (size_t)i * 2 + 1);

    uint4 o;
    o.x = pack2(a.x, a.y);
    o.y = pack2(a.z, a.w);
    o.z = pack2(b.x, b.y);
    o.w = pack2(b.z, b.w);

    st_tab16(reinterpret_cast<uint4*>(dst) + i, o, pol);
}

// ---------------------------------------------------------------------------
// gather kernel: 4 lanes per sample; lane q reads 16B at
//   (row i1 / i2, col j1 or j2 (q>=2), channel chunk q&1) of BOTH tables.
// i-blend and j-blend in packed half2; fp32 only at the final store.
// ---------------------------------------------------------------------------
__global__ __launch_bounds__(256)
void dualbiplane_kernel(const int*    __restrict__ m,
                        const float2* __restrict__ h,
                        const float*  __restrict__ u,
                        const float*  __restrict__ v,
                        float*        __restrict__ out,
                        int N)
{
    int t = blockIdx.x * blockDim.x + threadIdx.x;
    int n = t >> 2;        // sample index
    int q = t & 3;         // lane within sample quad
    if (n >= N) return;

    int    mi = __ldcs(m + n);
    float2 hh = __ldcs(h + n);
    float  uu = __ldcs(u + n);
    float  vv = __ldcs(v + n);

    // index computation mirrors the reference exactly
    float ix = (hh.x + 1.0f) * 0.5f * 400.0f; if (ix == 400.0f) ix = 399.0f;
    float iy = (hh.y + 1.0f) * 0.5f * 400.0f; if (iy == 400.0f) iy = 399.0f;
    float iu = uu * 400.0f;                   if (iu == 400.0f) iu = 399.0f;
    float iv = vv * 400.0f;                   if (iv == 400.0f) iv = 399.0f;

    int   xi1 = (int)floorf(ix), xj1 = (int)floorf(iy);
    float xir = ix - (float)xi1, xjr = iy - (float)xj1;
    int   xi2 = xi1 + 1; if (xi2 == RES) xi2 = 0;
    int   xj2 = xj1 + 1; if (xj2 == RES) xj2 = 0;

    int   ui1 = (int)floorf(iu), uj1 = (int)floorf(iv);
    float uir = iu - (float)ui1, ujr = iv - (float)uj1;
    int   ui2 = ui1 + 1; if (ui2 == RES) ui2 = 0;
    int   uj2 = uj1 + 1; if (uj2 == RES) uj2 = 0;

    bool hi = (q >= 2);          // handles the j2 corner slices
    int  c  = q & 1;             // channel chunk: 0 -> ch0-7, 1 -> ch8-15

    int xjs = hi ? xj2 : xj1;
    int ujs = hi ? uj2 : uj1;

    const uint4* TX = reinterpret_cast<const uint4*>(g_Fxy_h);
    const uint4* TU = reinterpret_cast<const uint4*>(g_Fuv_h);

    int base = mi * (RES * RES);
    uint4 A = __ldcg(TX + ((size_t)(base + xi1 * RES + xjs)) * 2 + c);
    uint4 B = __ldcg(TX + ((size_t)(base + xi2 * RES + xjs)) * 2 + c);
    uint4 C = __ldcg(TU + ((size_t)(base + ui1 * RES + ujs)) * 2 + c);
    uint4 D = __ldcg(TU + ((size_t)(base + ui2 * RES + ujs)) * 2 + c);

    // ---- i-blend in half2 ----
    __half2 wx1 = __float2half2_rn(xir);
    __half2 wx0 = __float2half2_rn(1.0f - xir);
    __half2 wu1 = __float2half2_rn(uir);
    __half2 wu0 = __float2half2_rn(1.0f - uir);

    const unsigned* aw = &A.x;
    const unsigned* bw = &B.x;
    const unsigned* cw = &C.x;
    const unsigned* dw = &D.x;

    unsigned txw[4], tuw[4];
#pragma unroll
    for (int k = 0; k < 4; k++) {
        __half2 tx = __hfma2(u2h2(bw[k]), wx1, __hmul2(u2h2(aw[k]), wx0));
        __half2 tu = __hfma2(u2h2(dw[k]), wu1, __hmul2(u2h2(cw[k]), wu0));
        txw[k] = h22u(tx);
        tuw[k] = h22u(tu);
    }

    // ---- j-blend via one packed shfl_xor(2) round ----
    // lo lanes (j1) own XY, need partner's XY j2 slice; they send their UV.
    // hi lanes (j2) own UV, need partner's UV j1 slice; they send their XY.
    float woF = hi ? ujr : (1.0f - xjr);   // weight on own slice
    float wrF = hi ? (1.0f - ujr) : xjr;   // weight on received slice
    __half2 wo2 = __float2half2_rn(woF);
    __half2 wr2 = __float2half2_rn(wrF);

    uint64_t p0, p1, p2, p3;
    {
        float2 f[4];
#pragma unroll
        for (int k = 0; k < 4; k++) {
            unsigned send = hi ? txw[k] : tuw[k];
            unsigned recv = __shfl_xor_sync(0xffffffffu, send, 2);
            __half2  own  = u2h2(hi ? tuw[k] : txw[k]);
            __half2  fin  = __hfma2(own, wo2, __hmul2(u2h2(recv), wr2));
            f[k] = __half22float2(fin);
        }
        p0 = pk64(f[0].x, f[0].y);
        p1 = pk64(f[1].x, f[1].y);
        p2 = pk64(f[2].x, f[2].y);
        p3 = pk64(f[3].x, f[3].y);
    }

    // Lane q owns 8 contiguous output floats:
    //   q=0: XY ch0-7   q=1: XY ch8-15   q=2: UV ch0-7   q=3: UV ch8-15
    float* dst = out + (size_t)n * 32 + q * 8;
    asm volatile("st.global.cs.v4.b64 [%0], {%1,%2,%3,%4};"
                 :: "l"(dst), "l"(p0), "l"(p1), "l"(p2), "l"(p3));
}

extern "C" void kernel_launch(void* const* d_in, const int* in_sizes, int n_in,
                              void* d_out, int out_size)
{
    const int*    m   = (const int*)   d_in[0];
    const float2* h   = (const float2*)d_in[1];
    const float*  u   = (const float*) d_in[2];
    const float*  v   = (const float*) d_in[3];
    const float4* Fxy = (const float4*)d_in[4];
    const float4* Fuv = (const float4*)d_in[5];

    int N = in_sizes[0];

    // 1) convert fp32 tables -> fp16 scratch (every launch; deterministic)
    {
        int total = 2 * (TAB_ELEMS / 8);
        convert_kernel<<<(total + 255) / 256, 256>>>(Fxy, Fuv);
    }

    // 2) gather
    {
        long long total_threads = (long long)N * 4;
        int blocks = (int)((total_threads + 255) / 256);
        dualbiplane_kernel<<<blocks, 256>>>(m, h, u, v, (float*)d_out, N);
    }
}